// round 11
// baseline (speedup 1.0000x reference)
#include <cuda_runtime.h>
#include <math.h>

#define NIMG     1024
#define CIN      3
#define HH       32
#define WWID     32
#define OF       64
#define KPATCH   27
#define THREADS  256
#define XS_PITCH 36   // padded row pitch; rows 8B-aligned

#define SELU_SCALE   1.0507009873554805f
#define SELU_AS      1.7580993408473766f   // scale * alpha

typedef unsigned long long u64;

__constant__ float cw [KPATCH * OF];  // conv weights (27, 64) row-major
__constant__ float cb [OF];           // bias
__constant__ float csp[CIN * OF];     // scale_proj (3, 64)
__constant__ float csb[OF];           // scale_bias

__device__ __forceinline__ u64 dup2(float v) {
    u64 r;
    asm("mov.b64 %0, {%1, %1};" : "=l"(r) : "f"(v));
    return r;
}
__device__ __forceinline__ u64 pack2(float a, float b) {
    u64 r;
    asm("mov.b64 %0, {%1, %2};" : "=l"(r) : "f"(a), "f"(b));
    return r;
}
__device__ __forceinline__ void unpack2(u64 v, float& a, float& b) {
    asm("mov.b64 {%0, %1}, %2;" : "=f"(a), "=f"(b) : "l"(v));
}
// Blackwell packed dual-FMA / dual-ADD.
__device__ __forceinline__ void fma2(u64& acc, u64 x, u64 w) {
    asm("fma.rn.f32x2 %0, %1, %2, %0;" : "+l"(acc) : "l"(x), "l"(w));
}
__device__ __forceinline__ u64 add2(u64 a, u64 b) {
    u64 r;
    asm("add.rn.f32x2 %0, %1, %2;" : "=l"(r) : "l"(a), "l"(b));
    return r;
}
// Single-MUFU sqrt (rel err ~1e-7, tolerance is 1e-3).
__device__ __forceinline__ float sqrt_ap(float x) {
    float r;
    asm("sqrt.approx.f32 %0, %1;" : "=f"(r) : "f"(x));
    return r;
}

// SELU; negative branch on MUFU pipe via __expf.
__device__ __forceinline__ float selu_f(float v) {
    float e   = __expf(v);
    float neg = fmaf(e, SELU_AS, -SELU_AS);
    return v > 0.0f ? SELU_SCALE * v : neg;
}

__global__ void __launch_bounds__(THREADS, 4) fused_conv_selu_pool_gate(
    const float* __restrict__ x,      // (1024, 3, 32, 32)
    float* __restrict__ out)          // (1024, 64)
{
    __shared__ __align__(16) float xs[CIN][34][XS_PITCH]; // image w/ halo
    __shared__ float gsh[OF];                             // gate
    __shared__ float red[8][OF];                          // per-warp partials
    __shared__ float csum_sh[8][CIN];                     // per-warp channel sums

    const int n    = blockIdx.x;
    const int tid  = threadIdx.x;
    const int lane = tid & 31;
    const int warp = tid >> 5;
    const float* xn = x + (size_t)n * (CIN * HH * WWID);

    // ---- stage image with zero halo; channel sums on the fly ----
    float cs0 = 0.f, cs1 = 0.f, cs2 = 0.f;
    for (int i = tid; i < CIN * 34 * 34; i += THREADS) {
        int c  = i / (34 * 34);
        int r  = i % (34 * 34);
        int hh = r / 34, ww = r % 34;
        float v = 0.f;
        if (hh >= 1 && hh <= 32 && ww >= 1 && ww <= 32) {
            v = xn[c * (HH * WWID) + (hh - 1) * WWID + (ww - 1)];
            if (c == 0)      cs0 += v;
            else if (c == 1) cs1 += v;
            else             cs2 += v;
        }
        xs[c][hh][ww] = v;
    }
    #pragma unroll
    for (int off = 16; off; off >>= 1) {
        cs0 += __shfl_xor_sync(0xffffffffu, cs0, off);
        cs1 += __shfl_xor_sync(0xffffffffu, cs1, off);
        cs2 += __shfl_xor_sync(0xffffffffu, cs2, off);
    }
    if (lane == 0) {
        csum_sh[warp][0] = cs0;
        csum_sh[warp][1] = cs1;
        csum_sh[warp][2] = cs2;
    }
    __syncthreads();

    // ---- gate: sigmoid(mean(x) @ scale_proj + scale_bias) ----
    if (tid < OF) {
        float s0 = 0.f, s1 = 0.f, s2 = 0.f;
        #pragma unroll
        for (int wz = 0; wz < 8; wz++) {
            s0 += csum_sh[wz][0];
            s1 += csum_sh[wz][1];
            s2 += csum_sh[wz][2];
        }
        const float inv = 1.0f / (HH * WWID);
        float z = s0 * inv * csp[0 * OF + tid]
                + s1 * inv * csp[1 * OF + tid]
                + s2 * inv * csp[2 * OF + tid]
                + csb[tid];
        gsh[tid] = 1.0f / (1.0f + __expf(-z));
    }
    __syncthreads();

    // Pair A covers output pixels (hA, w0), (hA, w0+1); pair B at hA+16.
    const int hA = tid >> 4;           // 0..15
    const int w0 = (tid & 15) << 1;    // 0..30
    const float* rowA0 = &xs[0][hA][w0];
    const float* rowB0 = rowA0 + 16 * XS_PITCH;

    // ---- main: conv + SELU + L2-pool(pairs along W) + spatial sum ----
    // Channels-in-lane: acc[px][j] lanes = channels (cg*8+2j, cg*8+2j+1).
    #pragma unroll 1
    for (int cg = 0; cg < 8; cg++) {
        u64 acc0[4], acc1[4], acc2[4], acc3[4];   // px0=A0, px1=A1, px2=B0, px3=B1
        {
            const ulonglong2* cbp = (const ulonglong2*)&cb[cg * 8];
            ulonglong2 q0 = cbp[0], q1 = cbp[1];
            acc0[0] = q0.x; acc0[1] = q0.y; acc0[2] = q1.x; acc0[3] = q1.y;
            #pragma unroll
            for (int j = 0; j < 4; j++) { acc1[j] = acc0[j]; acc2[j] = acc0[j]; acc3[j] = acc0[j]; }
        }

        const float* rA = rowA0;
        const float* rB = rowB0;
        const float* wrow = cw + cg * 8;     // advance 3*64 floats per body

        #pragma unroll 1
        for (int c = 0; c < 3; c++) {
            #pragma unroll 1
            for (int dy = 0; dy < 3; dy++) {
                float2 fa0 = *(const float2*)(rA);       // x[w0], x[w0+1]
                float2 fa1 = *(const float2*)(rA + 2);   // x[w0+2], x[w0+3]
                float2 fb0 = *(const float2*)(rB);
                float2 fb1 = *(const float2*)(rB + 2);
                u64 xA[4], xB[4];
                xA[0] = dup2(fa0.x); xA[1] = dup2(fa0.y);
                xA[2] = dup2(fa1.x); xA[3] = dup2(fa1.y);
                xB[0] = dup2(fb0.x); xB[1] = dup2(fb0.y);
                xB[2] = dup2(fb1.x); xB[3] = dup2(fb1.y);

                #pragma unroll
                for (int dx = 0; dx < 3; dx++) {
                    const ulonglong2* wp = (const ulonglong2*)(wrow + dx * OF);
                    ulonglong2 w01 = wp[0];   // channel pairs via constant port
                    ulonglong2 w23 = wp[1];
                    fma2(acc0[0], xA[dx],     w01.x);
                    fma2(acc0[1], xA[dx],     w01.y);
                    fma2(acc0[2], xA[dx],     w23.x);
                    fma2(acc0[3], xA[dx],     w23.y);
                    fma2(acc1[0], xA[dx + 1], w01.x);
                    fma2(acc1[1], xA[dx + 1], w01.y);
                    fma2(acc1[2], xA[dx + 1], w23.x);
                    fma2(acc1[3], xA[dx + 1], w23.y);
                    fma2(acc2[0], xB[dx],     w01.x);
                    fma2(acc2[1], xB[dx],     w01.y);
                    fma2(acc2[2], xB[dx],     w23.x);
                    fma2(acc2[3], xB[dx],     w23.y);
                    fma2(acc3[0], xB[dx + 1], w01.x);
                    fma2(acc3[1], xB[dx + 1], w01.y);
                    fma2(acc3[2], xB[dx + 1], w23.x);
                    fma2(acc3[3], xB[dx + 1], w23.y);
                }
                rA += XS_PITCH;
                rB += XS_PITCH;
                wrow += 3 * OF;
            }
            rA += (34 - 3) * XS_PITCH;   // next channel plane
            rB += (34 - 3) * XS_PITCH;
        }

        // SELU + pair-L2 (approx sqrt) + packed warp reduction.
        #pragma unroll
        for (int j = 0; j < 4; j++) {
            float a0l, a0h, a1l, a1h, b0l, b0h, b1l, b1h;
            unpack2(acc0[j], a0l, a0h);
            unpack2(acc1[j], a1l, a1h);
            unpack2(acc2[j], b0l, b0h);
            unpack2(acc3[j], b1l, b1h);
            a0l = selu_f(a0l); a0h = selu_f(a0h);
            a1l = selu_f(a1l); a1h = selu_f(a1h);
            b0l = selu_f(b0l); b0h = selu_f(b0h);
            b1l = selu_f(b1l); b1h = selu_f(b1h);
            float vl = sqrt_ap(fmaf(a1l, a1l, a0l * a0l)) + sqrt_ap(fmaf(b1l, b1l, b0l * b0l));
            float vh = sqrt_ap(fmaf(a1h, a1h, a0h * a0h)) + sqrt_ap(fmaf(b1h, b1h, b0h * b0h));
            u64 pv = pack2(vl, vh);
            #pragma unroll
            for (int off = 16; off; off >>= 1)
                pv = add2(pv, __shfl_xor_sync(0xffffffffu, pv, off));
            if (lane == 0) {
                unpack2(pv, vl, vh);
                red[warp][cg * 8 + 2 * j]     = vl;
                red[warp][cg * 8 + 2 * j + 1] = vh;
            }
        }
    }

    __syncthreads();   // single barrier for the whole main phase
    if (tid < OF) {
        float s = 0.f;
        #pragma unroll
        for (int wz = 0; wz < 8; wz++) s += red[wz][tid];
        out[n * OF + tid] = s * (1.0f / 512.0f) * gsh[tid];
    }
}

extern "C" void kernel_launch(void* const* d_in, const int* in_sizes, int n_in,
                              void* d_out, int out_size) {
    const float* x      = (const float*)d_in[0];
    const float* weight = (const float*)d_in[1];
    const float* bias   = (const float*)d_in[2];
    const float* sproj  = (const float*)d_in[3];
    const float* sbias  = (const float*)d_in[4];
    float* out = (float*)d_out;

    cudaMemcpyToSymbolAsync(cw,  weight, KPATCH * OF * sizeof(float), 0, cudaMemcpyDeviceToDevice, 0);
    cudaMemcpyToSymbolAsync(cb,  bias,   OF * sizeof(float),          0, cudaMemcpyDeviceToDevice, 0);
    cudaMemcpyToSymbolAsync(csp, sproj,  CIN * OF * sizeof(float),    0, cudaMemcpyDeviceToDevice, 0);
    cudaMemcpyToSymbolAsync(csb, sbias,  OF * sizeof(float),          0, cudaMemcpyDeviceToDevice, 0);

    fused_conv_selu_pool_gate<<<NIMG, THREADS>>>(x, out);
}

// round 12
// speedup vs baseline: 1.0847x; 1.0847x over previous
#include <cuda_runtime.h>
#include <math.h>

#define NIMG     1024
#define CIN      3
#define HH       32
#define WWID     32
#define OF       64
#define KPATCH   27
#define THREADS  256
#define IMGS_PER_CTA 2
#define GRID     (NIMG / IMGS_PER_CTA)
#define XS_PITCH 36   // padded row pitch; rows 8B-aligned

#define SELU_SCALE   1.0507009873554805f
#define SELU_AS      1.7580993408473766f   // scale * alpha

typedef unsigned long long u64;

__constant__ float cw [KPATCH * OF];  // conv weights (27, 64) row-major
__constant__ float cb [OF];           // bias
__constant__ float csp[CIN * OF];     // scale_proj (3, 64)
__constant__ float csb[OF];           // scale_bias

__device__ __forceinline__ u64 dup2(float v) {
    u64 r;
    asm("mov.b64 %0, {%1, %1};" : "=l"(r) : "f"(v));
    return r;
}
__device__ __forceinline__ void unpack2(u64 v, float& a, float& b) {
    asm("mov.b64 {%0, %1}, %2;" : "=f"(a), "=f"(b) : "l"(v));
}
// Blackwell packed dual-FMA: 2 fp32 FMAs per instruction.
__device__ __forceinline__ void fma2(u64& acc, u64 x, u64 w) {
    asm("fma.rn.f32x2 %0, %1, %2, %0;" : "+l"(acc) : "l"(x), "l"(w));
}
// Single-MUFU sqrt (rel err ~1e-7; tolerance is 1e-3).
__device__ __forceinline__ float sqrt_ap(float x) {
    float r;
    asm("sqrt.approx.f32 %0, %1;" : "=f"(r) : "f"(x));
    return r;
}

// SELU; negative branch on MUFU pipe via __expf.
__device__ __forceinline__ float selu_f(float v) {
    float e   = __expf(v);
    float neg = fmaf(e, SELU_AS, -SELU_AS);
    return v > 0.0f ? SELU_SCALE * v : neg;
}

__global__ void __launch_bounds__(THREADS, 4) fused_conv_selu_pool_gate(
    const float* __restrict__ x,      // (1024, 3, 32, 32)
    float* __restrict__ out)          // (1024, 64)
{
    __shared__ __align__(16) float xs[CIN][34][XS_PITCH]; // image w/ halo
    __shared__ float gsh[OF];                             // gate
    __shared__ float red[8][OF];                          // per-warp partials
    __shared__ float csum_sh[8][CIN];                     // per-warp channel sums

    const int tid  = threadIdx.x;
    const int lane = tid & 31;
    const int warp = tid >> 5;

    // Pair A covers output pixels (hA, w0), (hA, w0+1); pair B at hA+16.
    const int hA = tid >> 4;           // 0..15
    const int w0 = (tid & 15) << 1;    // 0..30
    const float* rowA0 = &xs[0][hA][w0];
    const float* rowB0 = rowA0 + 16 * XS_PITCH;

    #pragma unroll 1
    for (int img = 0; img < IMGS_PER_CTA; img++) {
        const int n = (blockIdx.x << 1) | img;
        const float* xn = x + (size_t)n * (CIN * HH * WWID);

        // ---- stage image with zero halo; channel sums on the fly ----
        float cs0 = 0.f, cs1 = 0.f, cs2 = 0.f;
        for (int i = tid; i < CIN * 34 * 34; i += THREADS) {
            int c  = i / (34 * 34);
            int r  = i % (34 * 34);
            int hh = r / 34, ww = r % 34;
            float v = 0.f;
            if (hh >= 1 && hh <= 32 && ww >= 1 && ww <= 32) {
                v = xn[c * (HH * WWID) + (hh - 1) * WWID + (ww - 1)];
                if (c == 0)      cs0 += v;
                else if (c == 1) cs1 += v;
                else             cs2 += v;
            }
            xs[c][hh][ww] = v;
        }
        #pragma unroll
        for (int off = 16; off; off >>= 1) {
            cs0 += __shfl_xor_sync(0xffffffffu, cs0, off);
            cs1 += __shfl_xor_sync(0xffffffffu, cs1, off);
            cs2 += __shfl_xor_sync(0xffffffffu, cs2, off);
        }
        if (lane == 0) {
            csum_sh[warp][0] = cs0;
            csum_sh[warp][1] = cs1;
            csum_sh[warp][2] = cs2;
        }
        __syncthreads();

        // ---- gate: sigmoid(mean(x) @ scale_proj + scale_bias) ----
        if (tid < OF) {
            float s0 = 0.f, s1 = 0.f, s2 = 0.f;
            #pragma unroll
            for (int wz = 0; wz < 8; wz++) {
                s0 += csum_sh[wz][0];
                s1 += csum_sh[wz][1];
                s2 += csum_sh[wz][2];
            }
            const float inv = 1.0f / (HH * WWID);
            float z = s0 * inv * csp[0 * OF + tid]
                    + s1 * inv * csp[1 * OF + tid]
                    + s2 * inv * csp[2 * OF + tid]
                    + csb[tid];
            gsh[tid] = 1.0f / (1.0f + __expf(-z));
        }
        __syncthreads();

        // ---- main: conv + SELU + L2-pool(pairs along W) + spatial sum ----
        // Channels-in-lane: acc[px][j] lanes = channels (cg*8+2j, cg*8+2j+1).
        #pragma unroll 1
        for (int cg = 0; cg < 8; cg++) {
            u64 acc0[4], acc1[4], acc2[4], acc3[4];   // px0=A0, px1=A1, px2=B0, px3=B1
            {
                const ulonglong2* cbp = (const ulonglong2*)&cb[cg * 8];
                ulonglong2 q0 = cbp[0], q1 = cbp[1];
                acc0[0] = q0.x; acc0[1] = q0.y; acc0[2] = q1.x; acc0[3] = q1.y;
                #pragma unroll
                for (int j = 0; j < 4; j++) { acc1[j] = acc0[j]; acc2[j] = acc0[j]; acc3[j] = acc0[j]; }
            }

            const float* rA = rowA0;
            const float* rB = rowB0;
            const float* wrow = cw + cg * 8;     // advance 3*64 floats per body

            #pragma unroll 1
            for (int c = 0; c < 3; c++) {
                #pragma unroll 1
                for (int dy = 0; dy < 3; dy++) {
                    float2 fa0 = *(const float2*)(rA);       // x[w0], x[w0+1]
                    float2 fa1 = *(const float2*)(rA + 2);   // x[w0+2], x[w0+3]
                    float2 fb0 = *(const float2*)(rB);
                    float2 fb1 = *(const float2*)(rB + 2);
                    u64 xA[4], xB[4];
                    xA[0] = dup2(fa0.x); xA[1] = dup2(fa0.y);
                    xA[2] = dup2(fa1.x); xA[3] = dup2(fa1.y);
                    xB[0] = dup2(fb0.x); xB[1] = dup2(fb0.y);
                    xB[2] = dup2(fb1.x); xB[3] = dup2(fb1.y);

                    #pragma unroll
                    for (int dx = 0; dx < 3; dx++) {
                        const ulonglong2* wp = (const ulonglong2*)(wrow + dx * OF);
                        ulonglong2 w01 = wp[0];   // channel pairs via constant port
                        ulonglong2 w23 = wp[1];
                        fma2(acc0[0], xA[dx],     w01.x);
                        fma2(acc0[1], xA[dx],     w01.y);
                        fma2(acc0[2], xA[dx],     w23.x);
                        fma2(acc0[3], xA[dx],     w23.y);
                        fma2(acc1[0], xA[dx + 1], w01.x);
                        fma2(acc1[1], xA[dx + 1], w01.y);
                        fma2(acc1[2], xA[dx + 1], w23.x);
                        fma2(acc1[3], xA[dx + 1], w23.y);
                        fma2(acc2[0], xB[dx],     w01.x);
                        fma2(acc2[1], xB[dx],     w01.y);
                        fma2(acc2[2], xB[dx],     w23.x);
                        fma2(acc2[3], xB[dx],     w23.y);
                        fma2(acc3[0], xB[dx + 1], w01.x);
                        fma2(acc3[1], xB[dx + 1], w01.y);
                        fma2(acc3[2], xB[dx + 1], w23.x);
                        fma2(acc3[3], xB[dx + 1], w23.y);
                    }
                    rA += XS_PITCH;
                    rB += XS_PITCH;
                    wrow += 3 * OF;
                }
                rA += (34 - 3) * XS_PITCH;   // next channel plane
                rB += (34 - 3) * XS_PITCH;
            }

            // SELU + pair-L2 (approx sqrt) + scalar warp reduce (two independent chains).
            #pragma unroll
            for (int j = 0; j < 4; j++) {
                float a0l, a0h, a1l, a1h, b0l, b0h, b1l, b1h;
                unpack2(acc0[j], a0l, a0h);
                unpack2(acc1[j], a1l, a1h);
                unpack2(acc2[j], b0l, b0h);
                unpack2(acc3[j], b1l, b1h);
                a0l = selu_f(a0l); a0h = selu_f(a0h);
                a1l = selu_f(a1l); a1h = selu_f(a1h);
                b0l = selu_f(b0l); b0h = selu_f(b0h);
                b1l = selu_f(b1l); b1h = selu_f(b1h);
                float vl = sqrt_ap(fmaf(a1l, a1l, a0l * a0l)) + sqrt_ap(fmaf(b1l, b1l, b0l * b0l));
                float vh = sqrt_ap(fmaf(a1h, a1h, a0h * a0h)) + sqrt_ap(fmaf(b1h, b1h, b0h * b0h));
                #pragma unroll
                for (int off = 16; off; off >>= 1) {
                    vl += __shfl_xor_sync(0xffffffffu, vl, off);
                    vh += __shfl_xor_sync(0xffffffffu, vh, off);
                }
                if (lane == 0) {
                    red[warp][cg * 8 + 2 * j]     = vl;
                    red[warp][cg * 8 + 2 * j + 1] = vh;
                }
            }
        }

        __syncthreads();   // single barrier for the whole main phase
        if (tid < OF) {
            float s = 0.f;
            #pragma unroll
            for (int wz = 0; wz < 8; wz++) s += red[wz][tid];
            out[n * OF + tid] = s * (1.0f / 512.0f) * gsh[tid];
        }
    }
}

extern "C" void kernel_launch(void* const* d_in, const int* in_sizes, int n_in,
                              void* d_out, int out_size) {
    const float* x      = (const float*)d_in[0];
    const float* weight = (const float*)d_in[1];
    const float* bias   = (const float*)d_in[2];
    const float* sproj  = (const float*)d_in[3];
    const float* sbias  = (const float*)d_in[4];
    float* out = (float*)d_out;

    cudaMemcpyToSymbolAsync(cw,  weight, KPATCH * OF * sizeof(float), 0, cudaMemcpyDeviceToDevice, 0);
    cudaMemcpyToSymbolAsync(cb,  bias,   OF * sizeof(float),          0, cudaMemcpyDeviceToDevice, 0);
    cudaMemcpyToSymbolAsync(csp, sproj,  CIN * OF * sizeof(float),    0, cudaMemcpyDeviceToDevice, 0);
    cudaMemcpyToSymbolAsync(csb, sbias,  OF * sizeof(float),          0, cudaMemcpyDeviceToDevice, 0);

    fused_conv_selu_pool_gate<<<GRID, THREADS>>>(x, out);
}

// round 13
// speedup vs baseline: 1.2139x; 1.1191x over previous
#include <cuda_runtime.h>
#include <math.h>

#define NIMG     1024
#define CIN      3
#define HH       32
#define WWID     32
#define OF       64
#define KPATCH   27
#define THREADS  256
#define XS_PITCH 36   // padded row pitch; rows 8B-aligned

#define SELU_SCALE   1.0507009873554805f
#define SELU_ALPHA   1.6732632423543772f

typedef unsigned long long u64;

__constant__ float cw [KPATCH * OF];  // conv weights (27, 64) row-major
__constant__ float cb [OF];           // bias
__constant__ float csp[CIN * OF];     // scale_proj (3, 64)
__constant__ float csb[OF];           // scale_bias

__device__ __forceinline__ u64 dup2(float v) {
    u64 r;
    asm("mov.b64 %0, {%1, %1};" : "=l"(r) : "f"(v));
    return r;
}
__device__ __forceinline__ void unpack2(u64 v, float& a, float& b) {
    asm("mov.b64 {%0, %1}, %2;" : "=f"(a), "=f"(b) : "l"(v));
}
// Blackwell packed dual-FMA: 2 fp32 FMAs per instruction.
__device__ __forceinline__ void fma2(u64& acc, u64 x, u64 w) {
    asm("fma.rn.f32x2 %0, %1, %2, %0;" : "+l"(acc) : "l"(x), "l"(w));
}
// Single-MUFU sqrt (rel err ~1e-7; tolerance is 1e-3).
__device__ __forceinline__ float sqrt_ap(float x) {
    float r;
    asm("sqrt.approx.f32 %0, %1;" : "=f"(r) : "f"(x));
    return r;
}

// Unscaled SELU core: u = v>0 ? v : alpha*(e^v - 1).
// SELU_SCALE is factored out of the L2 pool (sqrt((s*a)^2+(s*b)^2) = s*sqrt(a^2+b^2))
// and folded into the final output constant.
__device__ __forceinline__ float selu_u(float v) {
    float e = __expf(v);
    float neg = fmaf(e, SELU_ALPHA, -SELU_ALPHA);
    return v > 0.0f ? v : neg;
}

__global__ void __launch_bounds__(THREADS, 3) fused_conv_selu_pool_gate(
    const float* __restrict__ x,      // (1024, 3, 32, 32)
    float* __restrict__ out)          // (1024, 64)
{
    __shared__ __align__(16) float xs[CIN][34][XS_PITCH]; // image w/ halo
    __shared__ float gsh[OF];                             // gate
    __shared__ float red[8][OF];                          // per-warp partials
    __shared__ float csum_sh[8][CIN];                     // per-warp channel sums

    const int n    = blockIdx.x;
    const int tid  = threadIdx.x;
    const int lane = tid & 31;
    const int warp = tid >> 5;
    const float* xn = x + (size_t)n * (CIN * HH * WWID);

    // ---- stage image with zero halo; channel sums on the fly ----
    float cs0 = 0.f, cs1 = 0.f, cs2 = 0.f;
    for (int i = tid; i < CIN * 34 * 34; i += THREADS) {
        int c  = i / (34 * 34);
        int r  = i % (34 * 34);
        int hh = r / 34, ww = r % 34;
        float v = 0.f;
        if (hh >= 1 && hh <= 32 && ww >= 1 && ww <= 32) {
            v = xn[c * (HH * WWID) + (hh - 1) * WWID + (ww - 1)];
            if (c == 0)      cs0 += v;
            else if (c == 1) cs1 += v;
            else             cs2 += v;
        }
        xs[c][hh][ww] = v;
    }
    #pragma unroll
    for (int off = 16; off; off >>= 1) {
        cs0 += __shfl_xor_sync(0xffffffffu, cs0, off);
        cs1 += __shfl_xor_sync(0xffffffffu, cs1, off);
        cs2 += __shfl_xor_sync(0xffffffffu, cs2, off);
    }
    if (lane == 0) {
        csum_sh[warp][0] = cs0;
        csum_sh[warp][1] = cs1;
        csum_sh[warp][2] = cs2;
    }
    __syncthreads();

    // ---- gate: sigmoid(mean(x) @ scale_proj + scale_bias) ----
    if (tid < OF) {
        float s0 = 0.f, s1 = 0.f, s2 = 0.f;
        #pragma unroll
        for (int wz = 0; wz < 8; wz++) {
            s0 += csum_sh[wz][0];
            s1 += csum_sh[wz][1];
            s2 += csum_sh[wz][2];
        }
        const float inv = 1.0f / (HH * WWID);
        float z = s0 * inv * csp[0 * OF + tid]
                + s1 * inv * csp[1 * OF + tid]
                + s2 * inv * csp[2 * OF + tid]
                + csb[tid];
        gsh[tid] = 1.0f / (1.0f + __expf(-z));
    }
    __syncthreads();

    // Pair A covers output pixels (hA, w0), (hA, w0+1); pair B at hA+16.
    const int hA = tid >> 4;           // 0..15
    const int w0 = (tid & 15) << 1;    // 0..30
    const float* rowA0 = &xs[0][hA][w0];
    const float* rowB0 = rowA0 + 16 * XS_PITCH;

    // ---- main: conv + SELU + L2-pool(pairs along W) + spatial sum ----
    // Channels-in-lane: acc[px][j] lanes = channels (cg*8+2j, cg*8+2j+1).
    #pragma unroll 1
    for (int cg = 0; cg < 8; cg++) {
        u64 acc0[4], acc1[4], acc2[4], acc3[4];   // px0=A0, px1=A1, px2=B0, px3=B1
        {
            const ulonglong2* cbp = (const ulonglong2*)&cb[cg * 8];
            ulonglong2 q0 = cbp[0], q1 = cbp[1];
            acc0[0] = q0.x; acc0[1] = q0.y; acc0[2] = q1.x; acc0[3] = q1.y;
            #pragma unroll
            for (int j = 0; j < 4; j++) { acc1[j] = acc0[j]; acc2[j] = acc0[j]; acc3[j] = acc0[j]; }
        }

        const float* rA = rowA0;
        const float* rB = rowB0;
        const float* wrow = cw + cg * 8;     // advance 3*64 floats per body

        #pragma unroll 1
        for (int c = 0; c < 3; c++) {
            #pragma unroll 1
            for (int dy = 0; dy < 3; dy++) {
                float2 fa0 = *(const float2*)(rA);       // x[w0], x[w0+1]
                float2 fa1 = *(const float2*)(rA + 2);   // x[w0+2], x[w0+3]
                float2 fb0 = *(const float2*)(rB);
                float2 fb1 = *(const float2*)(rB + 2);
                u64 xA[4], xB[4];
                xA[0] = dup2(fa0.x); xA[1] = dup2(fa0.y);
                xA[2] = dup2(fa1.x); xA[3] = dup2(fa1.y);
                xB[0] = dup2(fb0.x); xB[1] = dup2(fb0.y);
                xB[2] = dup2(fb1.x); xB[3] = dup2(fb1.y);

                #pragma unroll
                for (int dx = 0; dx < 3; dx++) {
                    const ulonglong2* wp = (const ulonglong2*)(wrow + dx * OF);
                    ulonglong2 w01 = wp[0];   // channel pairs via constant port
                    ulonglong2 w23 = wp[1];
                    fma2(acc0[0], xA[dx],     w01.x);
                    fma2(acc0[1], xA[dx],     w01.y);
                    fma2(acc0[2], xA[dx],     w23.x);
                    fma2(acc0[3], xA[dx],     w23.y);
                    fma2(acc1[0], xA[dx + 1], w01.x);
                    fma2(acc1[1], xA[dx + 1], w01.y);
                    fma2(acc1[2], xA[dx + 1], w23.x);
                    fma2(acc1[3], xA[dx + 1], w23.y);
                    fma2(acc2[0], xB[dx],     w01.x);
                    fma2(acc2[1], xB[dx],     w01.y);
                    fma2(acc2[2], xB[dx],     w23.x);
                    fma2(acc2[3], xB[dx],     w23.y);
                    fma2(acc3[0], xB[dx + 1], w01.x);
                    fma2(acc3[1], xB[dx + 1], w01.y);
                    fma2(acc3[2], xB[dx + 1], w23.x);
                    fma2(acc3[3], xB[dx + 1], w23.y);
                }
                rA += XS_PITCH;
                rB += XS_PITCH;
                wrow += 3 * OF;
            }
            rA += (34 - 3) * XS_PITCH;   // next channel plane
            rB += (34 - 3) * XS_PITCH;
        }

        // Unscaled SELU + pair-L2 (approx sqrt) + scalar warp reduce.
        #pragma unroll
        for (int j = 0; j < 4; j++) {
            float a0l, a0h, a1l, a1h, b0l, b0h, b1l, b1h;
            unpack2(acc0[j], a0l, a0h);
            unpack2(acc1[j], a1l, a1h);
            unpack2(acc2[j], b0l, b0h);
            unpack2(acc3[j], b1l, b1h);
            a0l = selu_u(a0l); a0h = selu_u(a0h);
            a1l = selu_u(a1l); a1h = selu_u(a1h);
            b0l = selu_u(b0l); b0h = selu_u(b0h);
            b1l = selu_u(b1l); b1h = selu_u(b1h);
            float vl = sqrt_ap(fmaf(a1l, a1l, a0l * a0l)) + sqrt_ap(fmaf(b1l, b1l, b0l * b0l));
            float vh = sqrt_ap(fmaf(a1h, a1h, a0h * a0h)) + sqrt_ap(fmaf(b1h, b1h, b0h * b0h));
            #pragma unroll
            for (int off = 16; off; off >>= 1) {
                vl += __shfl_xor_sync(0xffffffffu, vl, off);
                vh += __shfl_xor_sync(0xffffffffu, vh, off);
            }
            if (lane == 0) {
                red[warp][cg * 8 + 2 * j]     = vl;
                red[warp][cg * 8 + 2 * j + 1] = vh;
            }
        }
    }

    __syncthreads();   // single barrier for the whole main phase
    if (tid < OF) {
        float s = 0.f;
        #pragma unroll
        for (int wz = 0; wz < 8; wz++) s += red[wz][tid];
        // SELU_SCALE factored out of the pool, folded in here.
        out[n * OF + tid] = s * (SELU_SCALE / 512.0f) * gsh[tid];
    }
}

extern "C" void kernel_launch(void* const* d_in, const int* in_sizes, int n_in,
                              void* d_out, int out_size) {
    const float* x      = (const float*)d_in[0];
    const float* weight = (const float*)d_in[1];
    const float* bias   = (const float*)d_in[2];
    const float* sproj  = (const float*)d_in[3];
    const float* sbias  = (const float*)d_in[4];
    float* out = (float*)d_out;

    cudaMemcpyToSymbolAsync(cw,  weight, KPATCH * OF * sizeof(float), 0, cudaMemcpyDeviceToDevice, 0);
    cudaMemcpyToSymbolAsync(cb,  bias,   OF * sizeof(float),          0, cudaMemcpyDeviceToDevice, 0);
    cudaMemcpyToSymbolAsync(csp, sproj,  CIN * OF * sizeof(float),    0, cudaMemcpyDeviceToDevice, 0);
    cudaMemcpyToSymbolAsync(csb, sbias,  OF * sizeof(float),          0, cudaMemcpyDeviceToDevice, 0);

    fused_conv_selu_pool_gate<<<NIMG, THREADS>>>(x, out);
}